// round 7
// baseline (speedup 1.0000x reference)
#include <cuda_runtime.h>
#include <cuda_bf16.h>
#include <cstdint>

// SphericalContraction (MipNeRF-360 eq. 10) + per-point 3x3 Jacobian.
//
//   m = ||p||
//   m <= 1 : out = p            J = I
//   m >  1 : s = 2/m - 1/m^2    out = s*p
//            c = 2(1-m)/m^4     J = s*I + c * p p^T
//
// Output layout (out_size = N*12 floats):
//   [0, 3N)   contracted points [N,3]
//   [3N,12N)  jacobians [N,3,3]
//
// R6: persistent kernel + double-buffered TMA pipeline.
//   - 1024 persistent blocks, each handling ntiles/1024 tiles of 512 points:
//     no wave transitions, no per-block launch/retire churn.
//   - input loads double-buffered via cp.async.bulk + mbarrier (prefetch t+2G)
//   - per-tile bulk stores committed as groups; wait_group.read (smem-read
//     completion only) lets GMEM writes drain fully async; one full
//     wait_group 0 per block at the end.
// smem = 2*6KB (in/oc, overwritten in place) + 18KB (jac) = 30KB -> 7 blocks/SM.

#define TILE_PTS 512
#define THREADS 256
#define GRID_BLOCKS 1024

#define IN_BYTES  (3 * TILE_PTS * 4)   // 6144
#define JAC_BYTES (9 * TILE_PTS * 4)   // 18432

__device__ __forceinline__ uint32_t smem_u32(const void* p) {
    return (uint32_t)__cvta_generic_to_shared(p);
}

__device__ __forceinline__ void mbar_wait(uint32_t mbar_a, uint32_t parity) {
    uint32_t done;
    asm volatile(
        "{\n\t.reg .pred p;\n\t"
        "mbarrier.try_wait.parity.acquire.cta.shared::cta.b64 p, [%1], %2;\n\t"
        "selp.b32 %0, 1, 0, p;\n\t}"
        : "=r"(done) : "r"(mbar_a), "r"(parity) : "memory");
    if (!done) {
        asm volatile(
            "{\n\t.reg .pred P1;\n\t"
            "WL_%=:\n\t"
            "mbarrier.try_wait.parity.acquire.cta.shared::cta.b64 P1, [%0], %1, 0x989680;\n\t"
            "@P1 bra.uni WD_%=;\n\t"
            "bra.uni WL_%=;\n\t"
            "WD_%=:\n\t}"
            :: "r"(mbar_a), "r"(parity) : "memory");
    }
}

__device__ __forceinline__ void contract_sc(float x, float y, float z,
                                            float& s, float& c) {
    float m2 = fmaf(x, x, fmaf(y, y, z * z));
    bool inside = (m2 <= 1.0f);          // m <= 1  <=>  m^2 <= 1 (no NaN risk)
    float inv  = rsqrtf(m2);             // 1/m (garbage if m2==0; unused then)
    float m    = m2 * inv;               // m
    s          = inv * (2.0f - inv);     // 2/m - 1/m^2
    float inv2 = inv * inv;
    c          = 2.0f * (1.0f - m) * inv2 * inv2;  // 2(1-m)/m^4
    if (inside) { s = 1.0f; c = 0.0f; }  // out = p, J = I
}

__global__ void __launch_bounds__(THREADS)
contract_jac_persist_kernel(const float* __restrict__ xin,
                            float* __restrict__ out_c,   // 3N floats
                            float* __restrict__ out_j,   // 9N floats
                            int ntiles)
{
    __shared__ alignas(16) float s_in[2][3 * TILE_PTS];  // 12 KB (oc in place)
    __shared__ alignas(16) float s_j[9 * TILE_PTS];      // 18 KB
    __shared__ alignas(8)  unsigned long long mbar[2];

    const int tid = threadIdx.x;
    const long bid = blockIdx.x;
    const long G = gridDim.x;
    const uint32_t mbar_a[2] = { smem_u32(&mbar[0]), smem_u32(&mbar[1]) };
    const uint32_t sin_a[2]  = { smem_u32(s_in[0]), smem_u32(s_in[1]) };
    const uint32_t sj_a      = smem_u32(s_j);

    if (tid == 0) {
        asm volatile("mbarrier.init.shared.b64 [%0], %1;"
                     :: "r"(mbar_a[0]), "r"(1u) : "memory");
        asm volatile("mbarrier.init.shared.b64 [%0], %1;"
                     :: "r"(mbar_a[1]), "r"(1u) : "memory");
    }
    __syncthreads();

    // ---- prologue: prefetch first two tiles ----
    if (tid == 0) {
#pragma unroll
        for (int p = 0; p < 2; ++p) {
            long t = bid + p * G;
            if (t < ntiles) {
                asm volatile("mbarrier.arrive.expect_tx.shared.b64 _, [%0], %1;"
                             :: "r"(mbar_a[p]), "r"((uint32_t)IN_BYTES) : "memory");
                asm volatile(
                    "cp.async.bulk.shared::cta.global.mbarrier::complete_tx::bytes "
                    "[%0], [%1], %2, [%3];"
                    :: "r"(sin_a[p]), "l"(xin + 3 * TILE_PTS * t),
                       "r"((uint32_t)IN_BYTES), "r"(mbar_a[p]) : "memory");
            }
        }
    }

    uint32_t phase[2] = {0u, 0u};
    int b = 0;
    for (long t = bid; t < ntiles; t += G, b ^= 1) {
        // ---- wait for this buffer's load ----
        mbar_wait(mbar_a[b], phase[b]);
        phase[b] ^= 1u;

        // ---- compute 2 points per thread ----
        float* sin = s_in[b];
#pragma unroll
        for (int j = 0; j < 2; ++j) {
            int q = tid + THREADS * j;
            float x = sin[3 * q + 0];    // stride 3: conflict-free
            float y = sin[3 * q + 1];
            float z = sin[3 * q + 2];

            float s, c;
            contract_sc(x, y, z, s, c);

            // contracted point overwrites this thread's own input slots
            sin[3 * q + 0] = s * x;
            sin[3 * q + 1] = s * y;
            sin[3 * q + 2] = s * z;

            float cx = c * x, cy = c * y, cz = c * z;
            float* jr = &s_j[9 * q];     // stride 9: conflict-free
            jr[0] = fmaf(cx, x, s);  jr[1] = cx * y;          jr[2] = cx * z;
            jr[3] = cy * x;          jr[4] = fmaf(cy, y, s);  jr[5] = cy * z;
            jr[6] = cz * x;          jr[7] = cz * y;          jr[8] = fmaf(cz, z, s);
        }
        __syncthreads();

        if (tid == 0) {
            // ---- bulk stores for this tile ----
            asm volatile("fence.proxy.async.shared::cta;" ::: "memory");
            asm volatile(
                "cp.async.bulk.global.shared::cta.bulk_group [%0], [%1], %2;"
                :: "l"(out_c + 3 * TILE_PTS * t), "r"(sin_a[b]),
                   "r"((uint32_t)IN_BYTES) : "memory");
            asm volatile(
                "cp.async.bulk.global.shared::cta.bulk_group [%0], [%1], %2;"
                :: "l"(out_j + 9 * TILE_PTS * t), "r"(sj_a),
                   "r"((uint32_t)JAC_BYTES) : "memory");
            asm volatile("cp.async.bulk.commit_group;" ::: "memory");
            // wait only for smem READS (frees s_in[b] and s_j for reuse);
            // GMEM writes keep draining in the background
            asm volatile("cp.async.bulk.wait_group.read 0;" ::: "memory");

            // ---- prefetch tile t+2G into the buffer just freed ----
            long tn = t + 2 * G;
            if (tn < ntiles) {
                asm volatile("mbarrier.arrive.expect_tx.shared.b64 _, [%0], %1;"
                             :: "r"(mbar_a[b]), "r"((uint32_t)IN_BYTES) : "memory");
                asm volatile(
                    "cp.async.bulk.shared::cta.global.mbarrier::complete_tx::bytes "
                    "[%0], [%1], %2, [%3];"
                    :: "r"(sin_a[b]), "l"(xin + 3 * TILE_PTS * tn),
                       "r"((uint32_t)IN_BYTES), "r"(mbar_a[b]) : "memory");
            }
        }
        __syncthreads();   // s_j / s_in[b] free only after wait_group.read
    }

    // ---- ensure all GMEM writes are visible before kernel completion ----
    if (tid == 0)
        asm volatile("cp.async.bulk.wait_group 0;" ::: "memory");
}

// Scalar tail / contract-only fallback.
__global__ void contract_jac_tail_kernel(const float* __restrict__ xin,
                                         float* __restrict__ out_c,
                                         float* __restrict__ out_j,  // may be null
                                         int start, int n) {
    int i = start + blockIdx.x * blockDim.x + threadIdx.x;
    if (i >= n) return;
    float x = xin[3 * i], y = xin[3 * i + 1], z = xin[3 * i + 2];
    float s, c;
    contract_sc(x, y, z, s, c);
    out_c[3 * i + 0] = s * x;
    out_c[3 * i + 1] = s * y;
    out_c[3 * i + 2] = s * z;
    if (out_j) {
        float cx = c * x, cy = c * y, cz = c * z;
        float* jr = &out_j[9 * (size_t)i];
        jr[0] = fmaf(cx, x, s);  jr[1] = cx * y;          jr[2] = cx * z;
        jr[3] = cy * x;          jr[4] = fmaf(cy, y, s);  jr[5] = cy * z;
        jr[6] = cz * x;          jr[7] = cz * y;          jr[8] = fmaf(cz, z, s);
    }
}

extern "C" void kernel_launch(void* const* d_in, const int* in_sizes, int n_in,
                              void* d_out, int out_size) {
    const float* x = (const float*)d_in[0];
    int n = in_sizes[0] / 3;                 // number of points
    float* out_c = (float*)d_out;
    bool want_jac = (out_size >= 12 * n);
    float* out_j = want_jac ? out_c + 3 * (size_t)n : nullptr;

    if (want_jac) {
        int ntiles = n / TILE_PTS;
        if (ntiles > 0) {
            int blocks = ntiles < GRID_BLOCKS ? ntiles : GRID_BLOCKS;
            contract_jac_persist_kernel<<<blocks, THREADS>>>(
                x, out_c, out_j, ntiles);
        }
        int done = ntiles * TILE_PTS;
        if (done < n) {
            int rem = n - done;
            contract_jac_tail_kernel<<<(rem + 255) / 256, 256>>>(
                x, out_c, out_j, done, n);
        }
    } else {
        contract_jac_tail_kernel<<<(n + 255) / 256, 256>>>(
            x, out_c, nullptr, 0, n);
    }
}

// round 8
// speedup vs baseline: 1.2076x; 1.2076x over previous
#include <cuda_runtime.h>
#include <cuda_bf16.h>

// SphericalContraction (MipNeRF-360 eq. 10) + per-point 3x3 Jacobian.
//
//   m = ||p||
//   m <= 1 : out = p            J = I
//   m >  1 : s = 2/m - 1/m^2    out = s*p
//            c = 2(1-m)/m^4     J = s*I + c * p p^T
//
// Output layout (out_size = N*12 floats):
//   [0, 3N)   contracted points [N,3]
//   [3N,12N)  jacobians [N,3,3]
//
// R7: R3 architecture (independent blocks, smem-staged, all-global-traffic
// as lane-consecutive float4) tuned for maximum concurrency:
//   - 256 pts / 128 threads / 12 KB smem -> 16 blocks/SM (100% warp cap),
//     16 phase-staggered pipelines per SM smoothing the DRAM write stream.
//   - contracted points overwrite the thread's own s_in slots during compute
//     (no cross-thread hazard) -> only 2 barriers per block.

#define PTS_PER_BLOCK 256
#define THREADS 128

#define IN_F4  (3 * PTS_PER_BLOCK / 4)   // 192 float4 (in / contracted)
#define JAC_F4 (9 * PTS_PER_BLOCK / 4)   // 576 float4

__device__ __forceinline__ void contract_sc(float x, float y, float z,
                                            float& s, float& c) {
    float m2 = fmaf(x, x, fmaf(y, y, z * z));
    bool inside = (m2 <= 1.0f);          // m <= 1  <=>  m^2 <= 1 (no NaN risk)
    float inv  = rsqrtf(m2);             // 1/m (garbage if m2==0; unused then)
    float m    = m2 * inv;               // m
    s          = inv * (2.0f - inv);     // 2/m - 1/m^2
    float inv2 = inv * inv;
    c          = 2.0f * (1.0f - m) * inv2 * inv2;  // 2(1-m)/m^4
    if (inside) { s = 1.0f; c = 0.0f; }  // out = p, J = I
}

__global__ void __launch_bounds__(THREADS)
contract_jac_smem_kernel(const float4* __restrict__ xin4,
                         float4* __restrict__ out_c4,  // 3N floats as float4
                         float4* __restrict__ out_j4)  // 9N floats as float4
{
    __shared__ float s_in[3 * PTS_PER_BLOCK];   // 3 KB (becomes contracted)
    __shared__ float s_j[9 * PTS_PER_BLOCK];    // 9 KB

    const int tid = threadIdx.x;
    const size_t base = (size_t)blockIdx.x * PTS_PER_BLOCK;

    // ---- coalesced input load: 192 float4 (1.5 / thread) ----
    const float4* src = xin4 + base * 3 / 4;
    float4* s_in4 = (float4*)s_in;
    s_in4[tid] = src[tid];
    if (tid < IN_F4 - THREADS) s_in4[THREADS + tid] = src[THREADS + tid];
    __syncthreads();

    // ---- compute 2 points per thread (q = tid, tid+128) ----
#pragma unroll
    for (int j = 0; j < 2; ++j) {
        int q = tid + THREADS * j;
        float x = s_in[3 * q + 0];     // stride 3: conflict-free
        float y = s_in[3 * q + 1];
        float z = s_in[3 * q + 2];

        float s, c;
        contract_sc(x, y, z, s, c);

        // contracted point overwrites this thread's own input slots
        s_in[3 * q + 0] = s * x;
        s_in[3 * q + 1] = s * y;
        s_in[3 * q + 2] = s * z;

        // jacobian (stride 9: conflict-free)
        float cx = c * x, cy = c * y, cz = c * z;
        float* jr = &s_j[9 * q];
        jr[0] = fmaf(cx, x, s);  jr[1] = cx * y;          jr[2] = cx * z;
        jr[3] = cy * x;          jr[4] = fmaf(cy, y, s);  jr[5] = cy * z;
        jr[6] = cz * x;          jr[7] = cz * y;          jr[8] = fmaf(cz, z, s);
    }
    __syncthreads();

    // ---- coalesced stores: contracted 192 f4, jacobian 576 f4 ----
    float4* dstc = out_c4 + base * 3 / 4;
    dstc[tid] = s_in4[tid];
    if (tid < IN_F4 - THREADS) dstc[THREADS + tid] = s_in4[THREADS + tid];

    const float4* s_j4 = (const float4*)s_j;
    float4* dstj = out_j4 + base * 9 / 4;
#pragma unroll
    for (int i = 0; i < 4; ++i)
        dstj[tid + THREADS * i] = s_j4[tid + THREADS * i];
    if (tid < JAC_F4 - 4 * THREADS)
        dstj[tid + THREADS * 4] = s_j4[tid + THREADS * 4];
}

// Scalar tail / contract-only fallback.
__global__ void contract_jac_tail_kernel(const float* __restrict__ xin,
                                         float* __restrict__ out_c,
                                         float* __restrict__ out_j,  // may be null
                                         int start, int n) {
    int i = start + blockIdx.x * blockDim.x + threadIdx.x;
    if (i >= n) return;
    float x = xin[3 * i], y = xin[3 * i + 1], z = xin[3 * i + 2];
    float s, c;
    contract_sc(x, y, z, s, c);
    out_c[3 * i + 0] = s * x;
    out_c[3 * i + 1] = s * y;
    out_c[3 * i + 2] = s * z;
    if (out_j) {
        float cx = c * x, cy = c * y, cz = c * z;
        float* jr = &out_j[9 * (size_t)i];
        jr[0] = fmaf(cx, x, s);  jr[1] = cx * y;          jr[2] = cx * z;
        jr[3] = cy * x;          jr[4] = fmaf(cy, y, s);  jr[5] = cy * z;
        jr[6] = cz * x;          jr[7] = cz * y;          jr[8] = fmaf(cz, z, s);
    }
}

extern "C" void kernel_launch(void* const* d_in, const int* in_sizes, int n_in,
                              void* d_out, int out_size) {
    const float* x = (const float*)d_in[0];
    int n = in_sizes[0] / 3;                 // number of points
    float* out_c = (float*)d_out;
    bool want_jac = (out_size >= 12 * n);
    float* out_j = want_jac ? out_c + 3 * (size_t)n : nullptr;

    if (want_jac) {
        int nfull = n / PTS_PER_BLOCK;
        if (nfull > 0) {
            contract_jac_smem_kernel<<<nfull, THREADS>>>(
                (const float4*)x, (float4*)out_c, (float4*)out_j);
        }
        int done = nfull * PTS_PER_BLOCK;
        if (done < n) {
            int rem = n - done;
            contract_jac_tail_kernel<<<(rem + 255) / 256, 256>>>(
                x, out_c, out_j, done, n);
        }
    } else {
        contract_jac_tail_kernel<<<(n + 255) / 256, 256>>>(
            x, out_c, nullptr, 0, n);
    }
}